// round 11
// baseline (speedup 1.0000x reference)
#include <cuda_runtime.h>
#include <stdint.h>
#include <math.h>

// Problem constants
#define BATCH 2
#define SEQ   2048
#define DIM   1024
#define HEADS 16
#define HD    64
#define MTOK  (BATCH * SEQ)            // 4096 tokens
#define HALF  (DIM / 2)                // 512

// tf32 GEMM tiling: CTA 128x256, 16 warps (2Mx8N), warp tile 64x32, K-chunk 32
#define GM 128
#define GN 256
#define GKC 32
#define NCHUNK (DIM / GKC)             // 32
#define NSTAGE 4
#define NTHR 512
#define RSTRIDE 144                     // padded row stride bytes (36 floats)
#define RA 0
#define RB (128 * RSTRIDE)              // 18432
#define STAGE_BYTES ((128 + 256) * RSTRIDE) // 55296
#define SMEM_TOTAL (NSTAGE * STAGE_BYTES)   // 221184 (< 227KB limit)

// ---------------------------------------------------------------------------
// Device scratch (no cudaMalloc allowed)
// ---------------------------------------------------------------------------
__device__ float g_q[MTOK * DIM];
__device__ float g_k[MTOK * DIM];
__device__ float g_v[MTOK * DIM];
__device__ float g_xx[MTOK * DIM];       // scrambled ctx (rna-rounded)
__device__ float g_xa[MTOK * DIM];       // rna(inputs)
__device__ float g_xc[MTOK * DIM];       // rna(context)
__device__ float g_cos[SEQ * HALF];
__device__ float g_sin[SEQ * HALF];
__device__ float g_invf[HALF];

__device__ float g_wq[DIM * DIM];        // transposed [N][K], rna-rounded
__device__ float g_wk[DIM * DIM];
__device__ float g_wv[DIM * DIM];
__device__ float g_wo[DIM * DIM];

// ---------------------------------------------------------------------------
// Helpers
// ---------------------------------------------------------------------------
__device__ __forceinline__ uint32_t smem_u32(const void* p) {
    uint32_t a;
    asm("{ .reg .u64 t; cvta.to.shared.u64 t, %1; cvt.u32.u64 %0, t; }"
        : "=r"(a) : "l"(p));
    return a;
}

__device__ __forceinline__ void cp16(uint32_t smem, const void* g) {
    asm volatile("cp.async.cg.shared.global [%0], [%1], 16;" :: "r"(smem), "l"(g));
}
__device__ __forceinline__ void cp_commit() {
    asm volatile("cp.async.commit_group;" ::: "memory");
}
template <int N>
__device__ __forceinline__ void cp_wait() {
    asm volatile("cp.async.wait_group %0;" :: "n"(N) : "memory");
}

__device__ __forceinline__ uint32_t lds_u32(uint32_t addr) {
    uint32_t v;
    asm volatile("ld.shared.b32 %0, [%1];" : "=r"(v) : "r"(addr));
    return v;
}
__device__ __forceinline__ float rna_f32(float x) {
    uint32_t u;
    asm("cvt.rna.tf32.f32 %0, %1;" : "=r"(u) : "f"(x));
    return __uint_as_float(u);
}

__device__ __forceinline__ void mma_tf32(float* d, const uint32_t* a,
                                         uint32_t b0, uint32_t b1) {
    asm volatile(
        "mma.sync.aligned.m16n8k8.row.col.f32.tf32.tf32.f32 "
        "{%0,%1,%2,%3}, {%4,%5,%6,%7}, {%8,%9}, {%0,%1,%2,%3};"
        : "+f"(d[0]), "+f"(d[1]), "+f"(d[2]), "+f"(d[3])
        : "r"(a[0]), "r"(a[1]), "r"(a[2]), "r"(a[3]), "r"(b0), "r"(b1));
}

// ---------------------------------------------------------------------------
// RoPE tables
// ---------------------------------------------------------------------------
__global__ void rope_inv_kernel() {
    int j = threadIdx.x;
    if (j < HALF) {
        double inv = exp(-((double)(2 * j) / (double)DIM) * log(10000.0));
        g_invf[j] = (float)inv;
    }
}

__global__ void rope_tab_kernel() {
    int idx = blockIdx.x * 256 + threadIdx.x;
    int s = idx >> 9;
    int j = idx & (HALF - 1);
    float arg = (float)s * g_invf[j];
    float sn, cs;
    sincosf(arg, &sn, &cs);
    g_cos[idx] = cs;
    g_sin[idx] = sn;
}

// ---------------------------------------------------------------------------
// Activations: fp32 -> RNA(tf32)-rounded fp32, same layout (float4)
// ---------------------------------------------------------------------------
__global__ void act_round_kernel(const float* __restrict__ X,
                                 float* __restrict__ Y) {
    int i = (blockIdx.x * 256 + threadIdx.x) * 4;
    float4 x = *(const float4*)(X + i);
    x.x = rna_f32(x.x); x.y = rna_f32(x.y);
    x.z = rna_f32(x.z); x.w = rna_f32(x.w);
    *(float4*)(Y + i) = x;
}

// ---------------------------------------------------------------------------
// All 4 weight transposes in ONE launch. blockIdx.z selects the matrix.
// W [K][N] fp32 -> transposed [N][K] fp32, RNA-rounded to tf32 precision.
// ---------------------------------------------------------------------------
__global__ void convert_w4_kernel(const float* __restrict__ W0,
                                  const float* __restrict__ W1,
                                  const float* __restrict__ W2,
                                  const float* __restrict__ W3) {
    __shared__ float t[32][33];
    const float* W = (blockIdx.z == 0) ? W0 : (blockIdx.z == 1) ? W1
                   : (blockIdx.z == 2) ? W2 : W3;
    float* T = (blockIdx.z == 0) ? g_wq : (blockIdx.z == 1) ? g_wk
             : (blockIdx.z == 2) ? g_wv : g_wo;
    int k0 = blockIdx.y * 32, n0 = blockIdx.x * 32;
    int tx = threadIdx.x, ty = threadIdx.y;   // 32 x 8
#pragma unroll
    for (int i = 0; i < 32; i += 8)
        t[ty + i][tx] = W[(size_t)(k0 + ty + i) * DIM + n0 + tx];
    __syncthreads();
#pragma unroll
    for (int i = 0; i < 32; i += 8) {
        float x = t[tx][ty + i];              // W[k0+tx][n0+ty+i]
        T[(size_t)(n0 + ty + i) * DIM + k0 + tx] = rna_f32(x);
    }
}

// ---------------------------------------------------------------------------
// tf32 GEMM body:  C[M,N] = A @ B^T + bias  (A, B pre-RNA-rounded)
// CTA 128x256, 512 threads, 16 warps (2Mx8N), warp tile 64x32, 4 stages.
// 16 warps = 4/SMSP: MMA issue interleaves 4 streams -> latency hidden.
// ~120 regs/thread so the 64K register file holds all 16 warps.
// Single barrier per chunk; register double-buffered fragments.
// ---------------------------------------------------------------------------
__device__ __forceinline__ void gemm_body(
    const float* __restrict__ A, const float* __restrict__ B,
    const float* __restrict__ bias, float* __restrict__ C,
    char* smem, int row0, int col0) {
    const int tid  = threadIdx.x;
    const int wid  = tid >> 5;
    const int lane = tid & 31;
    const uint32_t sb = smem_u32(smem);

    const int wm = wid >> 3;            // 0..1
    const int wn = wid & 7;             // 0..7
    const int m_base = wm * 64;
    const int n_base = wn * 32;

    float acc[4][4][4];
#pragma unroll
    for (int i = 0; i < 4; i++)
#pragma unroll
        for (int j = 0; j < 4; j++)
#pragma unroll
            for (int e = 0; e < 4; e++) acc[i][j][e] = 0.0f;

    auto issue = [&](int c) {
        const uint32_t st = sb + (uint32_t)(c & (NSTAGE - 1)) * STAGE_BYTES;
        const int k0 = c * GKC;
#pragma unroll
        for (int i = 0; i < 2; i++) {
            int seg = tid + i * NTHR;
            int r  = seg >> 3;
            int s8 = seg & 7;
            cp16(st + RA + r * RSTRIDE + s8 * 16,
                 A + (size_t)(row0 + r) * DIM + k0 + s8 * 4);
        }
#pragma unroll
        for (int i = 0; i < 4; i++) {
            int seg = tid + i * NTHR;
            int r  = seg >> 3;
            int s8 = seg & 7;
            cp16(st + RB + r * RSTRIDE + s8 * 16,
                 B + (size_t)(col0 + r) * DIM + k0 + s8 * 4);
        }
        cp_commit();
    };

    issue(0); issue(1); issue(2);

    for (int c = 0; c < NCHUNK; c++) {
        cp_wait<2>();
        __syncthreads();
        // stage (c+3)%4 == (c-1)%4: all readers passed the barrier above.
        if (c + 3 < NCHUNK) issue(c + 3);

        const uint32_t st = sb + (uint32_t)(c & (NSTAGE - 1)) * STAGE_BYTES;
        const uint32_t abase = st + RA + (m_base + (lane >> 2)) * RSTRIDE + (lane & 3) * 4;
        const uint32_t bbase = st + RB + (n_base + (lane >> 2)) * RSTRIDE + (lane & 3) * 4;

        uint32_t af[2][4][4], bf[2][4][2];

        auto load_frags = [&](int ks, int buf) {
            const int kb = ks * 32;
#pragma unroll
            for (int mi = 0; mi < 4; mi++) {
                uint32_t base = abase + mi * (16 * RSTRIDE) + kb;
                af[buf][mi][0] = lds_u32(base);
                af[buf][mi][1] = lds_u32(base + 8 * RSTRIDE);
                af[buf][mi][2] = lds_u32(base + 16);
                af[buf][mi][3] = lds_u32(base + 8 * RSTRIDE + 16);
            }
#pragma unroll
            for (int nj = 0; nj < 4; nj++) {
                uint32_t base = bbase + nj * (8 * RSTRIDE) + kb;
                bf[buf][nj][0] = lds_u32(base);
                bf[buf][nj][1] = lds_u32(base + 16);
            }
        };

        load_frags(0, 0);
#pragma unroll
        for (int ks = 0; ks < 4; ks++) {
            if (ks < 3) load_frags(ks + 1, (ks + 1) & 1);
            const int cb = ks & 1;
#pragma unroll
            for (int mi = 0; mi < 4; mi++)
#pragma unroll
                for (int nj = 0; nj < 4; nj++)
                    mma_tf32(acc[mi][nj], af[cb][mi], bf[cb][nj][0], bf[cb][nj][1]);
        }
    }

    // Epilogue: add bias, store fp32
    const int rw = row0 + m_base;
    const int cw = col0 + n_base;
#pragma unroll
    for (int nj = 0; nj < 4; nj++) {
        int n = cw + nj * 8 + (lane & 3) * 2;
        float bx = __ldg(&bias[n]);
        float by = __ldg(&bias[n + 1]);
#pragma unroll
        for (int mi = 0; mi < 4; mi++) {
            int r = rw + mi * 16 + (lane >> 2);
            float2 v0 = make_float2(acc[mi][nj][0] + bx, acc[mi][nj][1] + by);
            float2 v1 = make_float2(acc[mi][nj][2] + bx, acc[mi][nj][3] + by);
            *(float2*)(C + (size_t)r * DIM + n)       = v0;
            *(float2*)(C + (size_t)(r + 8) * DIM + n) = v1;
        }
    }
}

// Fused Q/K/V projections: blockIdx.z selects {A, W, bias, C}.
__global__ void __launch_bounds__(NTHR, 1)
gemm_qkv(const float* __restrict__ bq, const float* __restrict__ bk,
         const float* __restrict__ bv) {
    extern __shared__ __align__(1024) char smem[];
    int z = blockIdx.z;
    const float* A    = (z == 0) ? g_xa : g_xc;
    const float* B    = (z == 0) ? g_wq : (z == 1) ? g_wk : g_wv;
    const float* bias = (z == 0) ? bq   : (z == 1) ? bk   : bv;
    float* C          = (z == 0) ? g_q  : (z == 1) ? g_k  : g_v;
    gemm_body(A, B, bias, C, smem, blockIdx.y * GM, blockIdx.x * GN);
}

// Generic single GEMM (used for the O projection).
__global__ void __launch_bounds__(NTHR, 1)
gemm_tf32(const float* __restrict__ A, const float* __restrict__ B,
          const float* __restrict__ bias, float* __restrict__ C) {
    extern __shared__ __align__(1024) char smem[];
    gemm_body(A, B, bias, C, smem, blockIdx.y * GM, blockIdx.x * GN);
}

// ---------------------------------------------------------------------------
// Per-token attention, vectorized: float4 I/O, padded qr/kr,
// shfl softmax, scrambled rna-rounded ctx store.
// ---------------------------------------------------------------------------
#define QKPAD 66

__global__ __launch_bounds__(256)
void attn_kernel(float* __restrict__ attn_out, int write_attn) {
    __shared__ float q[DIM], k[DIM], v[DIM];
    __shared__ float qr[HEADS * QKPAD], kr[HEADS * QKPAD];
    __shared__ float sc[256];

    int t   = blockIdx.x;
    int b   = t >> 11;
    int s   = t & (SEQ - 1);
    int tid = threadIdx.x;
    int d   = tid * 4;

    ((float4*)q)[tid] = ((const float4*)(g_q + (size_t)t * DIM))[tid];
    ((float4*)k)[tid] = ((const float4*)(g_k + (size_t)t * DIM))[tid];
    ((float4*)v)[tid] = ((const float4*)(g_v + (size_t)t * DIM))[tid];
    __syncthreads();

    {
        int j  = d & (HALF - 1);
        int pd = (d < HALF) ? d + HALF : d - HALF;
        float sgn = (d < HALF) ? -1.0f : 1.0f;
        float4 c4 = *(const float4*)(g_cos + (size_t)s * HALF + j);
        float4 s4 = *(const float4*)(g_sin + (size_t)s * HALF + j);
        float4 qv = *(float4*)(q + d),  qp = *(float4*)(q + pd);
        float4 kv = *(float4*)(k + d),  kp = *(float4*)(k + pd);
        int row = d >> 6, e = d & 63;
        float* qd = qr + row * QKPAD + e;
        float* kd = kr + row * QKPAD + e;
        qd[0] = qv.x * c4.x + sgn * qp.x * s4.x;
        qd[1] = qv.y * c4.y + sgn * qp.y * s4.y;
        qd[2] = qv.z * c4.z + sgn * qp.z * s4.z;
        qd[3] = qv.w * c4.w + sgn * qp.w * s4.w;
        kd[0] = kv.x * c4.x + sgn * kp.x * s4.x;
        kd[1] = kv.y * c4.y + sgn * kp.y * s4.y;
        kd[2] = kv.z * c4.z + sgn * kp.z * s4.z;
        kd[3] = kv.w * c4.w + sgn * kp.w * s4.w;
    }
    __syncthreads();

    {
        int i = tid >> 4, j = tid & 15;
        const float* qp = qr + i * QKPAD;
        const float* kp = kr + j * QKPAD;
        float sum = 0.0f;
#pragma unroll
        for (int e = 0; e < HD; e++) sum += qp[e] * kp[e];
        sum *= 0.125f;
        float m = sum;
#pragma unroll
        for (int off = 8; off > 0; off >>= 1)
            m = fmaxf(m, __shfl_xor_sync(0xFFFFFFFFu, m, off, 16));
        float ex = expf(sum - m);
        float tot = ex;
#pragma unroll
        for (int off = 8; off > 0; off >>= 1)
            tot += __shfl_xor_sync(0xFFFFFFFFu, tot, off, 16);
        float p = ex / tot;
        sc[tid] = p;
        if (write_attn) attn_out[(size_t)t * 256 + tid] = p;
    }
    __syncthreads();

    {
        int i = d >> 6, e = d & 63;
        float4 acc = make_float4(0.f, 0.f, 0.f, 0.f);
        const float* pr = sc + i * 16;
#pragma unroll
        for (int j = 0; j < HEADS; j++) {
            float p = pr[j];
            float4 vv = *(float4*)(v + j * HD + e);
            acc.x += p * vv.x; acc.y += p * vv.y;
            acc.z += p * vv.z; acc.w += p * vv.w;
        }
        int r = i * (SEQ / HEADS) + (s >> 4);
        int c = ((s & 15) << 6) | e;
        acc.x = rna_f32(acc.x); acc.y = rna_f32(acc.y);
        acc.z = rna_f32(acc.z); acc.w = rna_f32(acc.w);
        *(float4*)(g_xx + (size_t)b * SEQ * DIM + (size_t)r * DIM + c) = acc;
    }
}

// ---------------------------------------------------------------------------
// Host launcher. Launch #4 == fused QKV GEMM  <-- ncu capture slot.
// ---------------------------------------------------------------------------
extern "C" void kernel_launch(void* const* d_in, const int* in_sizes, int n_in,
                              void* d_out, int out_size) {
    const float* inputs  = (const float*)d_in[0];
    const float* context = (const float*)d_in[1];
    const float* Wq = (const float*)d_in[2];
    const float* bq = (const float*)d_in[3];
    const float* Wk = (const float*)d_in[4];
    const float* bk = (const float*)d_in[5];
    const float* Wv = (const float*)d_in[6];
    const float* bv = (const float*)d_in[7];
    const float* Wo = (const float*)d_in[8];
    const float* bo = (const float*)d_in[9];
    float* out = (float*)d_out;

    cudaFuncSetAttribute(gemm_qkv, cudaFuncAttributeMaxDynamicSharedMemorySize,
                         SMEM_TOTAL);
    cudaFuncSetAttribute(gemm_tf32, cudaFuncAttributeMaxDynamicSharedMemorySize,
                         SMEM_TOTAL);

    float *pxx, *pxa, *pxc, *pwo;
    cudaGetSymbolAddress((void**)&pxx, g_xx);
    cudaGetSymbolAddress((void**)&pxa, g_xa);
    cudaGetSymbolAddress((void**)&pxc, g_xc);
    cudaGetSymbolAddress((void**)&pwo, g_wo);

    const int out_elems  = MTOK * DIM;
    const int attn_elems = MTOK * HEADS * HEADS;
    int write_attn = (out_size >= out_elems + attn_elems) ? 1 : 0;
    float* attn_out = out + out_elems;

    // #1: weight transposes (one launch)
    convert_w4_kernel<<<dim3(32, 32, 4), dim3(32, 8)>>>(Wq, Wk, Wv, Wo);
    // #2-3: activation pre-rounding
    act_round_kernel<<<(MTOK * DIM) / 1024, 256>>>(inputs,  pxa);
    act_round_kernel<<<(MTOK * DIM) / 1024, 256>>>(context, pxc);
    // #4: fused Q/K/V projections  <-- ncu capture slot
    gemm_qkv<<<dim3(DIM / GN, MTOK / GM, 3), NTHR, SMEM_TOTAL>>>(bq, bk, bv);
    // #5-6: RoPE tables
    rope_inv_kernel<<<1, 512>>>();
    rope_tab_kernel<<<(SEQ * HALF) / 256, 256>>>();
    // #7: RoPE + per-token head attention + scramble
    attn_kernel<<<MTOK, 256>>>(attn_out, write_attn);
    // #8: O projection
    gemm_tf32<<<dim3(DIM / GN, MTOK / GM), NTHR, SMEM_TOTAL>>>(pxx, pwo, bo, out);
}

// round 12
// speedup vs baseline: 1.0881x; 1.0881x over previous
#include <cuda_runtime.h>
#include <stdint.h>
#include <math.h>

// Problem constants
#define BATCH 2
#define SEQ   2048
#define DIM   1024
#define HEADS 16
#define HD    64
#define MTOK  (BATCH * SEQ)            // 4096 tokens
#define HALF  (DIM / 2)                // 512

// tf32 GEMM tiling: CTA 128x256, 8 warps (2Mx4N), warp tile 64x64, K-chunk 32
#define GM 128
#define GN 256
#define GKC 32
#define NCHUNK (DIM / GKC)             // 32
#define NSTAGE 4
#define RSTRIDE 144                     // padded row stride bytes (36 floats)
#define RA 0
#define RB (128 * RSTRIDE)              // 18432
#define STAGE_BYTES ((128 + 256) * RSTRIDE) // 55296
#define SMEM_TOTAL (NSTAGE * STAGE_BYTES)   // 221184 (< 227KB limit)

// ---------------------------------------------------------------------------
// Device scratch (no cudaMalloc allowed)
// ---------------------------------------------------------------------------
__device__ float g_q[MTOK * DIM];
__device__ float g_k[MTOK * DIM];
__device__ float g_v[MTOK * DIM];
__device__ float g_xx[MTOK * DIM];       // scrambled ctx
__device__ float g_cos[SEQ * HALF];
__device__ float g_sin[SEQ * HALF];

__device__ float g_wq[DIM * DIM];        // transposed [N][K], rna-rounded
__device__ float g_wk[DIM * DIM];
__device__ float g_wv[DIM * DIM];
__device__ float g_wo[DIM * DIM];

// ---------------------------------------------------------------------------
// Helpers
// ---------------------------------------------------------------------------
__device__ __forceinline__ uint32_t smem_u32(const void* p) {
    uint32_t a;
    asm("{ .reg .u64 t; cvta.to.shared.u64 t, %1; cvt.u32.u64 %0, t; }"
        : "=r"(a) : "l"(p));
    return a;
}

__device__ __forceinline__ void cp16(uint32_t smem, const void* g) {
    asm volatile("cp.async.cg.shared.global [%0], [%1], 16;" :: "r"(smem), "l"(g));
}
__device__ __forceinline__ void cp_commit() {
    asm volatile("cp.async.commit_group;" ::: "memory");
}
template <int N>
__device__ __forceinline__ void cp_wait() {
    asm volatile("cp.async.wait_group %0;" :: "n"(N) : "memory");
}

__device__ __forceinline__ uint32_t lds_u32(uint32_t addr) {
    uint32_t v;
    asm volatile("ld.shared.b32 %0, [%1];" : "=r"(v) : "r"(addr));
    return v;
}
__device__ __forceinline__ uint32_t f2tf32_u(uint32_t bits) {
    uint32_t u;
    asm("cvt.rna.tf32.f32 %0, %1;" : "=r"(u) : "f"(__uint_as_float(bits)));
    return u;
}
__device__ __forceinline__ float rna_f32(float x) {
    uint32_t u;
    asm("cvt.rna.tf32.f32 %0, %1;" : "=r"(u) : "f"(x));
    return __uint_as_float(u);
}

__device__ __forceinline__ void mma_tf32(float* d, const uint32_t* a,
                                         uint32_t b0, uint32_t b1) {
    asm volatile(
        "mma.sync.aligned.m16n8k8.row.col.f32.tf32.tf32.f32 "
        "{%0,%1,%2,%3}, {%4,%5,%6,%7}, {%8,%9}, {%0,%1,%2,%3};"
        : "+f"(d[0]), "+f"(d[1]), "+f"(d[2]), "+f"(d[3])
        : "r"(a[0]), "r"(a[1]), "r"(a[2]), "r"(a[3]), "r"(b0), "r"(b1));
}

// ---------------------------------------------------------------------------
// RoPE tables — single fused kernel, fp32 throughout (matches the reference's
// own fp32 power/outer computation). inv_freq = 2^(-2j/1024 * log2(10000)).
// ---------------------------------------------------------------------------
__global__ void rope_tab_kernel() {
    int idx = blockIdx.x * 256 + threadIdx.x;
    int s = idx >> 9;
    int j = idx & (HALF - 1);
    // log2(10000)/1024 * 2 = 0.025952563241303614
    float inv = exp2f((float)j * -0.025952563241303614f);
    float arg = (float)s * inv;
    float sn, cs;
    sincosf(arg, &sn, &cs);
    g_cos[idx] = cs;
    g_sin[idx] = sn;
}

// ---------------------------------------------------------------------------
// All 4 weight transposes in ONE launch. blockIdx.z selects the matrix.
// W [K][N] fp32 -> transposed [N][K] fp32, RNA-rounded to tf32 precision.
// ---------------------------------------------------------------------------
__global__ void convert_w4_kernel(const float* __restrict__ W0,
                                  const float* __restrict__ W1,
                                  const float* __restrict__ W2,
                                  const float* __restrict__ W3) {
    __shared__ float t[32][33];
    const float* W = (blockIdx.z == 0) ? W0 : (blockIdx.z == 1) ? W1
                   : (blockIdx.z == 2) ? W2 : W3;
    float* T = (blockIdx.z == 0) ? g_wq : (blockIdx.z == 1) ? g_wk
             : (blockIdx.z == 2) ? g_wv : g_wo;
    int k0 = blockIdx.y * 32, n0 = blockIdx.x * 32;
    int tx = threadIdx.x, ty = threadIdx.y;   // 32 x 8
#pragma unroll
    for (int i = 0; i < 32; i += 8)
        t[ty + i][tx] = W[(size_t)(k0 + ty + i) * DIM + n0 + tx];
    __syncthreads();
#pragma unroll
    for (int i = 0; i < 32; i += 8) {
        float x = t[tx][ty + i];              // W[k0+tx][n0+ty+i]
        T[(size_t)(n0 + ty + i) * DIM + k0 + tx] = rna_f32(x);
    }
}

// ---------------------------------------------------------------------------
// tf32 GEMM body:  C[M,N] = rna(A) @ B^T + bias
// A: raw fp32 (RNA applied to fragments in-register after LDS — idempotent
// if A is already rounded). B: pre-rounded transposed weights.
// CTA 128x256, 8 warps (2Mx4N), warp tile 64x64, K-chunk 32, 4 stages,
// single barrier per chunk, register double-buffered fragments.
// ---------------------------------------------------------------------------
__device__ __forceinline__ void gemm_body(
    const float* __restrict__ A, const float* __restrict__ B,
    const float* __restrict__ bias, float* __restrict__ C,
    char* smem, int row0, int col0) {
    const int tid  = threadIdx.x;
    const int wid  = tid >> 5;
    const int lane = tid & 31;
    const uint32_t sb = smem_u32(smem);

    const int wm = wid >> 2;            // 0..1
    const int wn = wid & 3;             // 0..3
    const int m_base = wm * 64;
    const int n_base = wn * 64;

    float acc[4][8][4];
#pragma unroll
    for (int i = 0; i < 4; i++)
#pragma unroll
        for (int j = 0; j < 8; j++)
#pragma unroll
            for (int e = 0; e < 4; e++) acc[i][j][e] = 0.0f;

    auto issue = [&](int c) {
        const uint32_t st = sb + (uint32_t)(c & (NSTAGE - 1)) * STAGE_BYTES;
        const int k0 = c * GKC;
#pragma unroll
        for (int i = 0; i < 4; i++) {
            int seg = tid + i * 256;
            int r  = seg >> 3;
            int s8 = seg & 7;
            cp16(st + RA + r * RSTRIDE + s8 * 16,
                 A + (size_t)(row0 + r) * DIM + k0 + s8 * 4);
        }
#pragma unroll
        for (int i = 0; i < 8; i++) {
            int seg = tid + i * 256;
            int r  = seg >> 3;
            int s8 = seg & 7;
            cp16(st + RB + r * RSTRIDE + s8 * 16,
                 B + (size_t)(col0 + r) * DIM + k0 + s8 * 4);
        }
        cp_commit();
    };

    issue(0); issue(1); issue(2);

    for (int c = 0; c < NCHUNK; c++) {
        cp_wait<2>();
        __syncthreads();
        // stage (c+3)%4 == (c-1)%4: all readers passed the barrier above.
        if (c + 3 < NCHUNK) issue(c + 3);

        const uint32_t st = sb + (uint32_t)(c & (NSTAGE - 1)) * STAGE_BYTES;
        const uint32_t abase = st + RA + (m_base + (lane >> 2)) * RSTRIDE + (lane & 3) * 4;
        const uint32_t bbase = st + RB + (n_base + (lane >> 2)) * RSTRIDE + (lane & 3) * 4;

        uint32_t af[2][4][4], bf[2][8][2];

        auto load_frags = [&](int ks, int buf) {
            const int kb = ks * 32;
#pragma unroll
            for (int mi = 0; mi < 4; mi++) {
                uint32_t base = abase + mi * (16 * RSTRIDE) + kb;
                af[buf][mi][0] = f2tf32_u(lds_u32(base));
                af[buf][mi][1] = f2tf32_u(lds_u32(base + 8 * RSTRIDE));
                af[buf][mi][2] = f2tf32_u(lds_u32(base + 16));
                af[buf][mi][3] = f2tf32_u(lds_u32(base + 8 * RSTRIDE + 16));
            }
#pragma unroll
            for (int nj = 0; nj < 8; nj++) {
                uint32_t base = bbase + nj * (8 * RSTRIDE) + kb;
                bf[buf][nj][0] = lds_u32(base);
                bf[buf][nj][1] = lds_u32(base + 16);
            }
        };

        load_frags(0, 0);
#pragma unroll
        for (int ks = 0; ks < 4; ks++) {
            if (ks < 3) load_frags(ks + 1, (ks + 1) & 1);
            const int cb = ks & 1;
#pragma unroll
            for (int mi = 0; mi < 4; mi++)
#pragma unroll
                for (int nj = 0; nj < 8; nj++)
                    mma_tf32(acc[mi][nj], af[cb][mi], bf[cb][nj][0], bf[cb][nj][1]);
        }
    }

    // Epilogue: add bias, store fp32
    const int rw = row0 + m_base;
    const int cw = col0 + n_base;
#pragma unroll
    for (int nj = 0; nj < 8; nj++) {
        int n = cw + nj * 8 + (lane & 3) * 2;
        float bx = __ldg(&bias[n]);
        float by = __ldg(&bias[n + 1]);
#pragma unroll
        for (int mi = 0; mi < 4; mi++) {
            int r = rw + mi * 16 + (lane >> 2);
            float2 v0 = make_float2(acc[mi][nj][0] + bx, acc[mi][nj][1] + by);
            float2 v1 = make_float2(acc[mi][nj][2] + bx, acc[mi][nj][3] + by);
            *(float2*)(C + (size_t)r * DIM + n)       = v0;
            *(float2*)(C + (size_t)(r + 8) * DIM + n) = v1;
        }
    }
}

// Fused Q/K/V projections: blockIdx.z selects {A, W, bias, C}.
// A operands are the RAW harness inputs — rounding happens in-register.
__global__ void __launch_bounds__(256, 1)
gemm_qkv(const float* __restrict__ inputs, const float* __restrict__ context,
         const float* __restrict__ bq, const float* __restrict__ bk,
         const float* __restrict__ bv) {
    extern __shared__ __align__(1024) char smem[];
    int z = blockIdx.z;
    const float* A    = (z == 0) ? inputs : context;
    const float* B    = (z == 0) ? g_wq : (z == 1) ? g_wk : g_wv;
    const float* bias = (z == 0) ? bq   : (z == 1) ? bk   : bv;
    float* C          = (z == 0) ? g_q  : (z == 1) ? g_k  : g_v;
    gemm_body(A, B, bias, C, smem, blockIdx.y * GM, blockIdx.x * GN);
}

// Generic single GEMM (used for the O projection).
__global__ void __launch_bounds__(256, 1)
gemm_tf32(const float* __restrict__ A, const float* __restrict__ B,
          const float* __restrict__ bias, float* __restrict__ C) {
    extern __shared__ __align__(1024) char smem[];
    gemm_body(A, B, bias, C, smem, blockIdx.y * GM, blockIdx.x * GN);
}

// ---------------------------------------------------------------------------
// Per-token attention, vectorized: float4 I/O, padded qr/kr,
// shfl softmax, scrambled ctx store (O-GEMM applies the tf32 rounding).
// ---------------------------------------------------------------------------
#define QKPAD 66

__global__ __launch_bounds__(256)
void attn_kernel(float* __restrict__ attn_out, int write_attn) {
    __shared__ float q[DIM], k[DIM], v[DIM];
    __shared__ float qr[HEADS * QKPAD], kr[HEADS * QKPAD];
    __shared__ float sc[256];

    int t   = blockIdx.x;
    int b   = t >> 11;
    int s   = t & (SEQ - 1);
    int tid = threadIdx.x;
    int d   = tid * 4;

    ((float4*)q)[tid] = ((const float4*)(g_q + (size_t)t * DIM))[tid];
    ((float4*)k)[tid] = ((const float4*)(g_k + (size_t)t * DIM))[tid];
    ((float4*)v)[tid] = ((const float4*)(g_v + (size_t)t * DIM))[tid];
    __syncthreads();

    {
        int j  = d & (HALF - 1);
        int pd = (d < HALF) ? d + HALF : d - HALF;
        float sgn = (d < HALF) ? -1.0f : 1.0f;
        float4 c4 = *(const float4*)(g_cos + (size_t)s * HALF + j);
        float4 s4 = *(const float4*)(g_sin + (size_t)s * HALF + j);
        float4 qv = *(float4*)(q + d),  qp = *(float4*)(q + pd);
        float4 kv = *(float4*)(k + d),  kp = *(float4*)(k + pd);
        int row = d >> 6, e = d & 63;
        float* qd = qr + row * QKPAD + e;
        float* kd = kr + row * QKPAD + e;
        qd[0] = qv.x * c4.x + sgn * qp.x * s4.x;
        qd[1] = qv.y * c4.y + sgn * qp.y * s4.y;
        qd[2] = qv.z * c4.z + sgn * qp.z * s4.z;
        qd[3] = qv.w * c4.w + sgn * qp.w * s4.w;
        kd[0] = kv.x * c4.x + sgn * kp.x * s4.x;
        kd[1] = kv.y * c4.y + sgn * kp.y * s4.y;
        kd[2] = kv.z * c4.z + sgn * kp.z * s4.z;
        kd[3] = kv.w * c4.w + sgn * kp.w * s4.w;
    }
    __syncthreads();

    {
        int i = tid >> 4, j = tid & 15;
        const float* qp = qr + i * QKPAD;
        const float* kp = kr + j * QKPAD;
        float sum = 0.0f;
#pragma unroll
        for (int e = 0; e < HD; e++) sum += qp[e] * kp[e];
        sum *= 0.125f;
        float m = sum;
#pragma unroll
        for (int off = 8; off > 0; off >>= 1)
            m = fmaxf(m, __shfl_xor_sync(0xFFFFFFFFu, m, off, 16));
        float ex = expf(sum - m);
        float tot = ex;
#pragma unroll
        for (int off = 8; off > 0; off >>= 1)
            tot += __shfl_xor_sync(0xFFFFFFFFu, tot, off, 16);
        float p = ex / tot;
        sc[tid] = p;
        if (write_attn) attn_out[(size_t)t * 256 + tid] = p;
    }
    __syncthreads();

    {
        int i = d >> 6, e = d & 63;
        float4 acc = make_float4(0.f, 0.f, 0.f, 0.f);
        const float* pr = sc + i * 16;
#pragma unroll
        for (int j = 0; j < HEADS; j++) {
            float p = pr[j];
            float4 vv = *(float4*)(v + j * HD + e);
            acc.x += p * vv.x; acc.y += p * vv.y;
            acc.z += p * vv.z; acc.w += p * vv.w;
        }
        int r = i * (SEQ / HEADS) + (s >> 4);
        int c = ((s & 15) << 6) | e;
        *(float4*)(g_xx + (size_t)b * SEQ * DIM + (size_t)r * DIM + c) = acc;
    }
}

// ---------------------------------------------------------------------------
// Host launcher. Launch #4 == attn_kernel  <-- ncu capture slot this round.
// ---------------------------------------------------------------------------
extern "C" void kernel_launch(void* const* d_in, const int* in_sizes, int n_in,
                              void* d_out, int out_size) {
    const float* inputs  = (const float*)d_in[0];
    const float* context = (const float*)d_in[1];
    const float* Wq = (const float*)d_in[2];
    const float* bq = (const float*)d_in[3];
    const float* Wk = (const float*)d_in[4];
    const float* bk = (const float*)d_in[5];
    const float* Wv = (const float*)d_in[6];
    const float* bv = (const float*)d_in[7];
    const float* Wo = (const float*)d_in[8];
    const float* bo = (const float*)d_in[9];
    float* out = (float*)d_out;

    cudaFuncSetAttribute(gemm_qkv, cudaFuncAttributeMaxDynamicSharedMemorySize,
                         SMEM_TOTAL);
    cudaFuncSetAttribute(gemm_tf32, cudaFuncAttributeMaxDynamicSharedMemorySize,
                         SMEM_TOTAL);

    float *pxx, *pwo;
    cudaGetSymbolAddress((void**)&pxx, g_xx);
    cudaGetSymbolAddress((void**)&pwo, g_wo);

    const int out_elems  = MTOK * DIM;
    const int attn_elems = MTOK * HEADS * HEADS;
    int write_attn = (out_size >= out_elems + attn_elems) ? 1 : 0;
    float* attn_out = out + out_elems;

    // #1: weight transposes (one launch)
    convert_w4_kernel<<<dim3(32, 32, 4), dim3(32, 8)>>>(Wq, Wk, Wv, Wo);
    // #2: RoPE tables (single fused kernel, fp32)
    rope_tab_kernel<<<(SEQ * HALF) / 256, 256>>>();
    // #3: fused Q/K/V projections (raw activations; rounding fused in-register)
    gemm_qkv<<<dim3(DIM / GN, MTOK / GM, 3), 256, SMEM_TOTAL>>>(
        inputs, context, bq, bk, bv);
    // #4: RoPE + per-token head attention + scramble  <-- ncu capture slot
    attn_kernel<<<MTOK, 256>>>(attn_out, write_attn);
    // #5: O projection
    gemm_tf32<<<dim3(DIM / GN, MTOK / GM), 256, SMEM_TOTAL>>>(pxx, pwo, bo, out);
}

// round 13
// speedup vs baseline: 1.0975x; 1.0086x over previous
#include <cuda_runtime.h>
#include <stdint.h>
#include <math.h>

// Problem constants
#define BATCH 2
#define SEQ   2048
#define DIM   1024
#define HEADS 16
#define HD    64
#define MTOK  (BATCH * SEQ)            // 4096 tokens
#define HALF  (DIM / 2)                // 512

// tf32 GEMM tiling: CTA 128x256, 8 warps (2Mx4N), warp tile 64x64, K-chunk 32
#define GM 128
#define GN 256
#define GKC 32
#define NCHUNK (DIM / GKC)             // 32
#define NSTAGE 4
#define RSTRIDE 144                     // padded row stride bytes (36 floats)
#define RA 0
#define RB (128 * RSTRIDE)              // 18432
#define STAGE_BYTES ((128 + 256) * RSTRIDE) // 55296
#define SMEM_TOTAL (NSTAGE * STAGE_BYTES)   // 221184 (< 227KB limit)

// ---------------------------------------------------------------------------
// Device scratch (no cudaMalloc allowed)
// ---------------------------------------------------------------------------
__device__ float g_q[MTOK * DIM];
__device__ float g_k[MTOK * DIM];
__device__ float g_v[MTOK * DIM];
__device__ float g_xx[MTOK * DIM];       // scrambled ctx
__device__ float g_cos[SEQ * HALF];
__device__ float g_sin[SEQ * HALF];

__device__ float g_wq[DIM * DIM];        // transposed [N][K], rna-rounded
__device__ float g_wk[DIM * DIM];
__device__ float g_wv[DIM * DIM];
__device__ float g_wo[DIM * DIM];

// ---------------------------------------------------------------------------
// Helpers
// ---------------------------------------------------------------------------
__device__ __forceinline__ uint32_t smem_u32(const void* p) {
    uint32_t a;
    asm("{ .reg .u64 t; cvta.to.shared.u64 t, %1; cvt.u32.u64 %0, t; }"
        : "=r"(a) : "l"(p));
    return a;
}

__device__ __forceinline__ void cp16(uint32_t smem, const void* g) {
    asm volatile("cp.async.cg.shared.global [%0], [%1], 16;" :: "r"(smem), "l"(g));
}
__device__ __forceinline__ void cp_commit() {
    asm volatile("cp.async.commit_group;" ::: "memory");
}
template <int N>
__device__ __forceinline__ void cp_wait() {
    asm volatile("cp.async.wait_group %0;" :: "n"(N) : "memory");
}

__device__ __forceinline__ uint32_t lds_u32(uint32_t addr) {
    uint32_t v;
    asm volatile("ld.shared.b32 %0, [%1];" : "=r"(v) : "r"(addr));
    return v;
}
__device__ __forceinline__ uint32_t f2tf32_u(uint32_t bits) {
    uint32_t u;
    asm("cvt.rna.tf32.f32 %0, %1;" : "=r"(u) : "f"(__uint_as_float(bits)));
    return u;
}
__device__ __forceinline__ float rna_f32(float x) {
    uint32_t u;
    asm("cvt.rna.tf32.f32 %0, %1;" : "=r"(u) : "f"(x));
    return __uint_as_float(u);
}

__device__ __forceinline__ void mma_tf32(float* d, const uint32_t* a,
                                         uint32_t b0, uint32_t b1) {
    asm volatile(
        "mma.sync.aligned.m16n8k8.row.col.f32.tf32.tf32.f32 "
        "{%0,%1,%2,%3}, {%4,%5,%6,%7}, {%8,%9}, {%0,%1,%2,%3};"
        : "+f"(d[0]), "+f"(d[1]), "+f"(d[2]), "+f"(d[3])
        : "r"(a[0]), "r"(a[1]), "r"(a[2]), "r"(a[3]), "r"(b0), "r"(b1));
}

// ---------------------------------------------------------------------------
// RoPE tables — fp32 throughout (matches the reference's fp32 power/outer).
// ---------------------------------------------------------------------------
__global__ void rope_tab_kernel() {
    int idx = blockIdx.x * 256 + threadIdx.x;
    int s = idx >> 9;
    int j = idx & (HALF - 1);
    float inv = exp2f((float)j * -0.025952563241303614f);  // 2*log2(1e4)/1024
    float arg = (float)s * inv;
    float sn, cs;
    sincosf(arg, &sn, &cs);
    g_cos[idx] = cs;
    g_sin[idx] = sn;
}

// ---------------------------------------------------------------------------
// All 4 weight transposes in ONE launch. blockIdx.z selects the matrix.
// W [K][N] fp32 -> transposed [N][K] fp32, RNA-rounded to tf32 precision.
// ---------------------------------------------------------------------------
__global__ void convert_w4_kernel(const float* __restrict__ W0,
                                  const float* __restrict__ W1,
                                  const float* __restrict__ W2,
                                  const float* __restrict__ W3) {
    __shared__ float t[32][33];
    const float* W = (blockIdx.z == 0) ? W0 : (blockIdx.z == 1) ? W1
                   : (blockIdx.z == 2) ? W2 : W3;
    float* T = (blockIdx.z == 0) ? g_wq : (blockIdx.z == 1) ? g_wk
             : (blockIdx.z == 2) ? g_wv : g_wo;
    int k0 = blockIdx.y * 32, n0 = blockIdx.x * 32;
    int tx = threadIdx.x, ty = threadIdx.y;   // 32 x 8
#pragma unroll
    for (int i = 0; i < 32; i += 8)
        t[ty + i][tx] = W[(size_t)(k0 + ty + i) * DIM + n0 + tx];
    __syncthreads();
#pragma unroll
    for (int i = 0; i < 32; i += 8) {
        float x = t[tx][ty + i];              // W[k0+tx][n0+ty+i]
        T[(size_t)(n0 + ty + i) * DIM + k0 + tx] = rna_f32(x);
    }
}

// ---------------------------------------------------------------------------
// tf32 GEMM body:  C[M,N] = rna(A) @ B^T + bias
// CTA 128x256, 8 warps (2Mx4N), warp tile 64x64, K-chunk 32, 4 stages,
// single barrier per chunk, register double-buffered fragments.
// ---------------------------------------------------------------------------
__device__ __forceinline__ void gemm_body(
    const float* __restrict__ A, const float* __restrict__ B,
    const float* __restrict__ bias, float* __restrict__ C,
    char* smem, int row0, int col0) {
    const int tid  = threadIdx.x;
    const int wid  = tid >> 5;
    const int lane = tid & 31;
    const uint32_t sb = smem_u32(smem);

    const int wm = wid >> 2;            // 0..1
    const int wn = wid & 3;             // 0..3
    const int m_base = wm * 64;
    const int n_base = wn * 64;

    float acc[4][8][4];
#pragma unroll
    for (int i = 0; i < 4; i++)
#pragma unroll
        for (int j = 0; j < 8; j++)
#pragma unroll
            for (int e = 0; e < 4; e++) acc[i][j][e] = 0.0f;

    auto issue = [&](int c) {
        const uint32_t st = sb + (uint32_t)(c & (NSTAGE - 1)) * STAGE_BYTES;
        const int k0 = c * GKC;
#pragma unroll
        for (int i = 0; i < 4; i++) {
            int seg = tid + i * 256;
            int r  = seg >> 3;
            int s8 = seg & 7;
            cp16(st + RA + r * RSTRIDE + s8 * 16,
                 A + (size_t)(row0 + r) * DIM + k0 + s8 * 4);
        }
#pragma unroll
        for (int i = 0; i < 8; i++) {
            int seg = tid + i * 256;
            int r  = seg >> 3;
            int s8 = seg & 7;
            cp16(st + RB + r * RSTRIDE + s8 * 16,
                 B + (size_t)(col0 + r) * DIM + k0 + s8 * 4);
        }
        cp_commit();
    };

    issue(0); issue(1); issue(2);

    for (int c = 0; c < NCHUNK; c++) {
        cp_wait<2>();
        __syncthreads();
        // stage (c+3)%4 == (c-1)%4: all readers passed the barrier above.
        if (c + 3 < NCHUNK) issue(c + 3);

        const uint32_t st = sb + (uint32_t)(c & (NSTAGE - 1)) * STAGE_BYTES;
        const uint32_t abase = st + RA + (m_base + (lane >> 2)) * RSTRIDE + (lane & 3) * 4;
        const uint32_t bbase = st + RB + (n_base + (lane >> 2)) * RSTRIDE + (lane & 3) * 4;

        uint32_t af[2][4][4], bf[2][8][2];

        auto load_frags = [&](int ks, int buf) {
            const int kb = ks * 32;
#pragma unroll
            for (int mi = 0; mi < 4; mi++) {
                uint32_t base = abase + mi * (16 * RSTRIDE) + kb;
                af[buf][mi][0] = f2tf32_u(lds_u32(base));
                af[buf][mi][1] = f2tf32_u(lds_u32(base + 8 * RSTRIDE));
                af[buf][mi][2] = f2tf32_u(lds_u32(base + 16));
                af[buf][mi][3] = f2tf32_u(lds_u32(base + 8 * RSTRIDE + 16));
            }
#pragma unroll
            for (int nj = 0; nj < 8; nj++) {
                uint32_t base = bbase + nj * (8 * RSTRIDE) + kb;
                bf[buf][nj][0] = lds_u32(base);
                bf[buf][nj][1] = lds_u32(base + 16);
            }
        };

        load_frags(0, 0);
#pragma unroll
        for (int ks = 0; ks < 4; ks++) {
            if (ks < 3) load_frags(ks + 1, (ks + 1) & 1);
            const int cb = ks & 1;
#pragma unroll
            for (int mi = 0; mi < 4; mi++)
#pragma unroll
                for (int nj = 0; nj < 8; nj++)
                    mma_tf32(acc[mi][nj], af[cb][mi], bf[cb][nj][0], bf[cb][nj][1]);
        }
    }

    // Epilogue: add bias, store fp32
    const int rw = row0 + m_base;
    const int cw = col0 + n_base;
#pragma unroll
    for (int nj = 0; nj < 8; nj++) {
        int n = cw + nj * 8 + (lane & 3) * 2;
        float bx = __ldg(&bias[n]);
        float by = __ldg(&bias[n + 1]);
#pragma unroll
        for (int mi = 0; mi < 4; mi++) {
            int r = rw + mi * 16 + (lane >> 2);
            float2 v0 = make_float2(acc[mi][nj][0] + bx, acc[mi][nj][1] + by);
            float2 v1 = make_float2(acc[mi][nj][2] + bx, acc[mi][nj][3] + by);
            *(float2*)(C + (size_t)r * DIM + n)       = v0;
            *(float2*)(C + (size_t)(r + 8) * DIM + n) = v1;
        }
    }
}

// Fused Q/K/V projections: blockIdx.z selects {A, W, bias, C}.
__global__ void __launch_bounds__(256, 1)
gemm_qkv(const float* __restrict__ inputs, const float* __restrict__ context,
         const float* __restrict__ bq, const float* __restrict__ bk,
         const float* __restrict__ bv) {
    extern __shared__ __align__(1024) char smem[];
    int z = blockIdx.z;
    const float* A    = (z == 0) ? inputs : context;
    const float* B    = (z == 0) ? g_wq : (z == 1) ? g_wk : g_wv;
    const float* bias = (z == 0) ? bq   : (z == 1) ? bk   : bv;
    float* C          = (z == 0) ? g_q  : (z == 1) ? g_k  : g_v;
    gemm_body(A, B, bias, C, smem, blockIdx.y * GM, blockIdx.x * GN);
}

// Generic single GEMM (used for the O projection).
__global__ void __launch_bounds__(256, 1)
gemm_tf32(const float* __restrict__ A, const float* __restrict__ B,
          const float* __restrict__ bias, float* __restrict__ C) {
    extern __shared__ __align__(1024) char smem[];
    gemm_body(A, B, bias, C, smem, blockIdx.y * GM, blockIdx.x * GN);
}

// ---------------------------------------------------------------------------
// Per-token attention v2 — RoPE applied DIRECTLY from global (no raw q/k
// staging round-trip through smem): each thread loads its float4 and its
// rotate-half partner float4 (both coalesced; partner is an L2 hit), writes
// only rotated qr/kr. Only v is staged. One fewer barrier, ~40% less L1
// traffic than v1.
// ---------------------------------------------------------------------------
#define QKPAD 66

__global__ __launch_bounds__(256)
void attn_kernel(float* __restrict__ attn_out, int write_attn) {
    __shared__ float v[DIM];
    __shared__ float qr[HEADS * QKPAD], kr[HEADS * QKPAD];
    __shared__ float sc[256];

    int t   = blockIdx.x;
    int b   = t >> 11;
    int s   = t & (SEQ - 1);
    int tid = threadIdx.x;
    int d   = tid * 4;

    // v: one float4 per thread into smem (needed cross-thread later)
    ((float4*)v)[tid] = ((const float4*)(g_v + (size_t)t * DIM))[tid];

    // RoPE directly from global q/k
    {
        int j  = d & (HALF - 1);
        int pd = (d < HALF) ? d + HALF : d - HALF;
        float sgn = (d < HALF) ? -1.0f : 1.0f;
        float4 c4 = *(const float4*)(g_cos + (size_t)s * HALF + j);
        float4 s4 = *(const float4*)(g_sin + (size_t)s * HALF + j);
        const float* qg = g_q + (size_t)t * DIM;
        const float* kg = g_k + (size_t)t * DIM;
        float4 qv = *(const float4*)(qg + d),  qp = *(const float4*)(qg + pd);
        float4 kv = *(const float4*)(kg + d),  kp = *(const float4*)(kg + pd);
        int row = d >> 6, e = d & 63;
        float* qd = qr + row * QKPAD + e;
        float* kd = kr + row * QKPAD + e;
        qd[0] = qv.x * c4.x + sgn * qp.x * s4.x;
        qd[1] = qv.y * c4.y + sgn * qp.y * s4.y;
        qd[2] = qv.z * c4.z + sgn * qp.z * s4.z;
        qd[3] = qv.w * c4.w + sgn * qp.w * s4.w;
        kd[0] = kv.x * c4.x + sgn * kp.x * s4.x;
        kd[1] = kv.y * c4.y + sgn * kp.y * s4.y;
        kd[2] = kv.z * c4.z + sgn * kp.z * s4.z;
        kd[3] = kv.w * c4.w + sgn * kp.w * s4.w;
    }
    __syncthreads();

    // Scores + softmax, one thread per (i,j); conflict-free padded reads.
    {
        int i = tid >> 4, j = tid & 15;
        const float* qp = qr + i * QKPAD;
        const float* kp = kr + j * QKPAD;
        float sum = 0.0f;
#pragma unroll
        for (int e = 0; e < HD; e++) sum += qp[e] * kp[e];
        sum *= 0.125f;
        float m = sum;
#pragma unroll
        for (int off = 8; off > 0; off >>= 1)
            m = fmaxf(m, __shfl_xor_sync(0xFFFFFFFFu, m, off, 16));
        float ex = expf(sum - m);
        float tot = ex;
#pragma unroll
        for (int off = 8; off > 0; off >>= 1)
            tot += __shfl_xor_sync(0xFFFFFFFFu, tot, off, 16);
        float p = ex / tot;
        sc[tid] = p;
        if (write_attn) attn_out[(size_t)t * 256 + tid] = p;
    }
    __syncthreads();

    // ctx + scrambled store: ctx[b,s,h,e] -> row h*128 + s/16, col (s%16)*64+e
    {
        int i = d >> 6, e = d & 63;
        float4 acc = make_float4(0.f, 0.f, 0.f, 0.f);
        const float* pr = sc + i * 16;
#pragma unroll
        for (int j = 0; j < HEADS; j++) {
            float p = pr[j];
            float4 vv = *(float4*)(v + j * HD + e);
            acc.x += p * vv.x; acc.y += p * vv.y;
            acc.z += p * vv.z; acc.w += p * vv.w;
        }
        int r = i * (SEQ / HEADS) + (s >> 4);
        int c = ((s & 15) << 6) | e;
        *(float4*)(g_xx + (size_t)b * SEQ * DIM + (size_t)r * DIM + c) = acc;
    }
}

// ---------------------------------------------------------------------------
// Host launcher. Launch #4 == attn_kernel  <-- ncu capture slot.
// ---------------------------------------------------------------------------
extern "C" void kernel_launch(void* const* d_in, const int* in_sizes, int n_in,
                              void* d_out, int out_size) {
    const float* inputs  = (const float*)d_in[0];
    const float* context = (const float*)d_in[1];
    const float* Wq = (const float*)d_in[2];
    const float* bq = (const float*)d_in[3];
    const float* Wk = (const float*)d_in[4];
    const float* bk = (const float*)d_in[5];
    const float* Wv = (const float*)d_in[6];
    const float* bv = (const float*)d_in[7];
    const float* Wo = (const float*)d_in[8];
    const float* bo = (const float*)d_in[9];
    float* out = (float*)d_out;

    cudaFuncSetAttribute(gemm_qkv, cudaFuncAttributeMaxDynamicSharedMemorySize,
                         SMEM_TOTAL);
    cudaFuncSetAttribute(gemm_tf32, cudaFuncAttributeMaxDynamicSharedMemorySize,
                         SMEM_TOTAL);

    float *pxx, *pwo;
    cudaGetSymbolAddress((void**)&pxx, g_xx);
    cudaGetSymbolAddress((void**)&pwo, g_wo);

    const int out_elems  = MTOK * DIM;
    const int attn_elems = MTOK * HEADS * HEADS;
    int write_attn = (out_size >= out_elems + attn_elems) ? 1 : 0;
    float* attn_out = out + out_elems;

    // #1: weight transposes (one launch)
    convert_w4_kernel<<<dim3(32, 32, 4), dim3(32, 8)>>>(Wq, Wk, Wv, Wo);
    // #2: RoPE tables
    rope_tab_kernel<<<(SEQ * HALF) / 256, 256>>>();
    // #3: fused Q/K/V projections (raw activations; rounding fused in-register)
    gemm_qkv<<<dim3(DIM / GN, MTOK / GM, 3), 256, SMEM_TOTAL>>>(
        inputs, context, bq, bk, bv);
    // #4: RoPE + per-token head attention + scramble  <-- ncu capture slot
    attn_kernel<<<MTOK, 256>>>(attn_out, write_attn);
    // #5: O projection
    gemm_tf32<<<dim3(DIM / GN, MTOK / GM), 256, SMEM_TOTAL>>>(pxx, pwo, bo, out);
}